// round 16
// baseline (speedup 1.0000x reference)
#include <cuda_runtime.h>
#include <cuda_bf16.h>
#include <math.h>
#include <stdint.h>

// ---------------- problem constants ----------------
#define FEAT   200
#define PADW   202
#define NPIX   (FEAT*FEAT)          // 40000
#define NPAD   (PADW*PADW)          // 40804
#define CCH    256
#define NA     9
#define NANCH  (NPIX*NA)            // 360000
#define TOPK   2000
#define OUTK   1000
#define NMS_TH 0.7f
#define BBOX_CLIP 4.135166556742356f
#define IMGSZ  1600.0f
#define SBITS  14
#define NBINS  (1 << (32 - SBITS))  // 262144 bins

// ---------------- packed f32x2 helpers (Blackwell FFMA2) ----------------
#define FMA2(acc, a, b) asm("fma.rn.f32x2 %0, %1, %2, %0;" : "+l"(acc) : "l"(a), "l"(b))

__device__ __forceinline__ unsigned long long splat2(float v) {
    unsigned long long r; asm("mov.b64 %0, {%1, %1};" : "=l"(r) : "f"(v)); return r;
}
__device__ __forceinline__ float2 unpack2(unsigned long long p) {
    float2 f; asm("mov.b64 {%0, %1}, %2;" : "=f"(f.x), "=f"(f.y) : "l"(p)); return f;
}

#define CP_ASYNC16(dst_u32, src_ptr) \
    asm volatile("cp.async.cg.shared.global [%0], [%1], 16;\n" :: "r"(dst_u32), "l"(src_ptr))
#define CP_COMMIT() asm volatile("cp.async.commit_group;\n")
#define CP_WAIT1()  asm volatile("cp.async.wait_group 1;\n")
#define CP_WAIT0()  asm volatile("cp.async.wait_group 0;\n")

// ---------------- scratch (device globals; no allocation allowed) ----------------
#define GAPAD 256
#define GTAIL 512
#define GATOT (GAPAD + CCH*NPAD + GTAIL)
__device__ __align__(16) float g_padA[GATOT];     // guarded padded feature map
__device__ __align__(16) float g_wT[2304*256];    // transposed conv weights [k][m]
__device__ float g_x[CCH*NPIX];          // relu(conv3x3) output, [c][p]
__device__ float g_boxes[NANCH*4];       // clipped proposals
__device__ unsigned g_key[NANCH];        // sortable sigmoid-score bits
__device__ __align__(16) unsigned g_hist14[NBINS]; // 18-bit-prefix histogram
__device__ unsigned g_state[4];          // [0]=threshold
__device__ unsigned g_cnt[4];            // [0]=pair count, [2]=valid count V
__device__ unsigned g_done[8];           // last-block-done counters
__device__ unsigned long long g_pairs[4096];
__device__ float g_sb[TOPK*4];           // boxes, valid-partitioned, rank order
__device__ float g_ss[TOPK];             // scores, same order
__device__ unsigned long long g_mask[TOPK*32];

// ---------------- 0: guard-padded feature map + weight transpose ----------------
__global__ void prep_kernel(const float* __restrict__ feat, const float* __restrict__ w) {
    int i = blockIdx.x*blockDim.x + threadIdx.x;
    if (i < GATOT) {
        float v = 0.f;
        int j = i - GAPAD;
        if (j >= 0 && j < CCH*NPAD) {
            int c = j / NPAD, q = j % NPAD;
            int y = q / PADW, x = q % PADW;
            if (y >= 1 && y <= FEAT && x >= 1 && x <= FEAT)
                v = feat[c*NPIX + (y-1)*FEAT + (x-1)];
        }
        g_padA[i] = v;
    } else {
        int j = i - GATOT;
        if (j < 2304*256) {
            int m = j / 2304, k = j % 2304;
            g_wT[k*256 + m] = w[j];
        }
    }
}

// ---------------- selection-state init (zero histogram + counters) ----------------
__global__ void init_kernel() {
    int i = blockIdx.x*blockDim.x + threadIdx.x;
    for (int j = i; j < NBINS; j += gridDim.x*blockDim.x) g_hist14[j] = 0;
    if (i < 4) g_cnt[i] = 0;
    if (i < 8) g_done[i] = 0;
    if (i == 0) { g_state[0] = 0; g_state[1] = TOPK; }
}

// ---------------- 1: conv3x3 + bias + relu, cp.async double-buffered implicit GEMM ----------------
#define BM 128
#define BN 144
#define TPX 9
#define BWIN 560   // per-channel pixel window [q0-208, q0+352)
#define CK 8
#define NCHUNK (CCH/CK)   // 32
__global__ __launch_bounds__(256, 2) void conv3_kernel(const float* __restrict__ bias) {
    __shared__ __align__(16) float sW[2][CK*9][BM];   // [buf][k in chunk][m]  (72 rows)
    __shared__ __align__(16) float sB[2][CK][BWIN];   // [buf][c][pixel window]
    const int tid = threadIdx.x;
    const int tx = tid & 15, ty = tid >> 4;
    const int m0 = blockIdx.y * BM;
    const int q0 = blockIdx.x * BN;
    const int p0 = tx * TPX;                          // 9 consecutive pixels per thread

    unsigned long long acc[4][TPX];
#pragma unroll
    for (int a = 0; a < 4; a++)
#pragma unroll
        for (int b = 0; b < TPX; b++) acc[a][b] = 0ull;

#define STAGE(BUF, CKI) do {                                                        \
        for (int idx = tid; idx < 2304; idx += 256) {                               \
            int row = idx >> 5, c8 = idx & 31;                                      \
            uint32_t d = (uint32_t)__cvta_generic_to_shared(&sW[BUF][row][c8*4]);   \
            const float* s = g_wT + ((CKI)*72 + row)*256 + m0 + c8*4;               \
            CP_ASYNC16(d, s);                                                       \
        }                                                                           \
        for (int idx = tid; idx < 1120; idx += 256) {                               \
            int c = idx / 140, o4 = idx % 140;                                      \
            uint32_t d = (uint32_t)__cvta_generic_to_shared(&sB[BUF][c][o4*4]);     \
            const float* s = g_padA + GAPAD + (size_t)((CKI)*CK + c)*NPAD           \
                             + (q0 - 208) + o4*4;                                   \
            CP_ASYNC16(d, s);                                                       \
        }                                                                           \
        CP_COMMIT();                                                                \
    } while (0)

    STAGE(0, 0);
    int buf = 0;
    for (int ck = 0; ck < NCHUNK; ck++) {
        if (ck + 1 < NCHUNK) { STAGE(buf ^ 1, ck + 1); CP_WAIT1(); }
        else                 { CP_WAIT0(); }
        __syncthreads();
#pragma unroll
        for (int c = 0; c < CK; c++) {
#pragma unroll
            for (int ky = 0; ky < 3; ky++) {
                const float* bb = &sB[buf][c][p0 + 202*ky + 5];
                unsigned long long spx[TPX + 2];
#pragma unroll
                for (int u = 0; u < TPX + 2; u++) spx[u] = splat2(bb[u]);
#pragma unroll
                for (int kx = 0; kx < 3; kx++) {
                    const int kk = c*9 + ky*3 + kx;
                    ulonglong2 WA = *(const ulonglong2*)&sW[buf][kk][ty*4];
                    ulonglong2 WB = *(const ulonglong2*)&sW[buf][kk][64 + ty*4];
#pragma unroll
                    for (int j = 0; j < TPX; j++) {
                        unsigned long long bs = spx[kx + j];
                        FMA2(acc[0][j], WA.x, bs);
                        FMA2(acc[1][j], WA.y, bs);
                        FMA2(acc[2][j], WB.x, bs);
                        FMA2(acc[3][j], WB.y, bs);
                    }
                }
            }
        }
        __syncthreads();
        buf ^= 1;
    }
#undef STAGE
#pragma unroll
    for (int cp = 0; cp < 4; cp++) {
        int mb = m0 + (cp >> 1)*64 + ty*4 + (cp & 1)*2;
        float bv0 = bias[mb], bv1 = bias[mb + 1];
#pragma unroll
        for (int j = 0; j < TPX; j++) {
            int q = q0 + p0 + j;
            if (q < NPAD) {
                int y = q / PADW, x = q % PADW;
                if (y >= 1 && y <= FEAT && x >= 1 && x <= FEAT) {
                    float2 v = unpack2(acc[cp][j]);
                    int p = (y-1)*FEAT + (x-1);
                    g_x[(size_t)mb*NPIX + p]     = fmaxf(v.x + bv0, 0.f);
                    g_x[(size_t)(mb+1)*NPIX + p] = fmaxf(v.y + bv1, 0.f);
                }
            }
        }
    }
}

// ---------------- 2: heads (45x256 GEMM, FFMA2) + anchors + deltas + clip + sigmoid ----------------
__device__ __forceinline__ void process_pixel(int p, float* L,
                                              const float* sbias) {
    if (p >= NPIX) return;
#pragma unroll
    for (int m = 0; m < 45; m++) L[m] += sbias[m];
    int y = p / FEAT, x = p % FEAT;
    float sx = x * 8.f, sy = y * 8.f;
#pragma unroll
    for (int a = 0; a < NA; a++) {
        int ai = a / 3, si = a % 3;
        float ar = (ai == 0) ? 0.5f : (ai == 1 ? 1.f : 2.f);
        float sc = (si == 0) ? 128.f : (si == 1 ? 256.f : 512.f);
        float hr = sqrtf(ar), wr = 1.f/hr;
        float ws = wr*sc, hs = hr*sc;
        float bx1 = rintf(-ws*0.5f), by1 = rintf(-hs*0.5f);
        float bx2 = rintf( ws*0.5f), by2 = rintf( hs*0.5f);
        float ax1 = sx + bx1, ay1 = sy + by1, ax2 = sx + bx2, ay2 = sy + by2;
        float w = ax2 - ax1, h = ay2 - ay1;
        float cx = ax1 + 0.5f*w, cy = ay1 + 0.5f*h;
        float dx = L[9 + a*4 + 0], dy = L[9 + a*4 + 1];
        float dw = fminf(L[9 + a*4 + 2], BBOX_CLIP);
        float dh = fminf(L[9 + a*4 + 3], BBOX_CLIP);
        float pcx = dx*w + cx, pcy = dy*h + cy;
        float pw = expf(dw)*w, ph = expf(dh)*h;
        float x1 = pcx - 0.5f*pw, y1 = pcy - 0.5f*ph;
        float x2 = pcx + 0.5f*pw, y2 = pcy + 0.5f*ph;
        x1 = fminf(fmaxf(x1, 0.f), IMGSZ);
        y1 = fminf(fmaxf(y1, 0.f), IMGSZ);
        x2 = fminf(fmaxf(x2, 0.f), IMGSZ);
        y2 = fminf(fmaxf(y2, 0.f), IMGSZ);
        int o = p*NA + a;
        g_boxes[o*4+0] = x1; g_boxes[o*4+1] = y1;
        g_boxes[o*4+2] = x2; g_boxes[o*4+3] = y2;
        float l = L[a];
        float s = 1.f / (1.f + expf(-l));
        g_key[o] = __float_as_uint(s);     // s in (0,1): bit pattern is order-preserving
    }
}

// 1 pixel/thread, block=128 (grid 313 -> 2 CTAs/SM), c-loop unrolled x8 (MLP=8). measured ~71us
#define HB 128
__global__ __launch_bounds__(HB) void heads_kernel(const float* __restrict__ clsw,
                                                   const float* __restrict__ clsb,
                                                   const float* __restrict__ regw,
                                                   const float* __restrict__ regb) {
    __shared__ __align__(16) unsigned long long sw2[CCH][24];
    __shared__ float sbias[48];
    const int tid = threadIdx.x;
    for (int i = tid; i < CCH*24; i += HB) {
        int c = i / 24, mp = i % 24;
        float v0 = 0.f, v1 = 0.f;
        int m0i = 2*mp, m1i = 2*mp + 1;
        if (m0i < 9)       v0 = clsw[m0i*CCH + c];
        else if (m0i < 45) v0 = regw[(m0i-9)*CCH + c];
        if (m1i < 9)       v1 = clsw[m1i*CCH + c];
        else if (m1i < 45) v1 = regw[(m1i-9)*CCH + c];
        unsigned long long pr;
        asm("mov.b64 %0, {%1, %2};" : "=l"(pr) : "f"(v0), "f"(v1));
        sw2[c][mp] = pr;
    }
    if (tid < 48) sbias[tid] = (tid < 9) ? clsb[tid] : ((tid < 45) ? regb[tid - 9] : 0.f);
    __syncthreads();

    int p = blockIdx.x*HB + tid;
    bool live = (p < NPIX);
    int pc = live ? p : 0;                  // clamp: dead threads compute garbage, never store
    unsigned long long A2[24];
#pragma unroll
    for (int m = 0; m < 24; m++) A2[m] = 0ull;
    for (int c = 0; c < CCH; c += 8) {
        // batch 8 independent loads up front (MLP=8)
        float xv[8];
#pragma unroll
        for (int u = 0; u < 8; u++) xv[u] = g_x[(size_t)(c+u)*NPIX + pc];
        unsigned long long xs[8];
#pragma unroll
        for (int u = 0; u < 8; u++) xs[u] = splat2(xv[u]);
#pragma unroll
        for (int u = 0; u < 8; u++) {
            const ulonglong2* wr = (const ulonglong2*)&sw2[c + u][0];
#pragma unroll
            for (int q = 0; q < 12; q++) {
                ulonglong2 wv = wr[q];
                FMA2(A2[2*q],   wv.x, xs[u]);
                FMA2(A2[2*q+1], wv.y, xs[u]);
            }
        }
    }
    float LA[48];
#pragma unroll
    for (int m = 0; m < 24; m++) {
        float2 v = unpack2(A2[m]);
        LA[2*m] = v.x; LA[2*m+1] = v.y;
    }
    process_pixel(live ? p : NPIX, LA, sbias);
}

// ---------------- 3: dedicated histogram pass (coalesced reads, spread REDG) ----------------
__global__ void hist14_kernel() {
    for (int i = blockIdx.x*blockDim.x + threadIdx.x; i < NANCH; i += gridDim.x*blockDim.x)
        atomicAdd(&g_hist14[g_key[i] >> SBITS], 1u);
}

// ---------------- 4: single-pass threshold pick over the 2^18-bin histogram ----------------
__global__ __launch_bounds__(1024) void pick14_kernel() {
    __shared__ unsigned s[1024];
    __shared__ unsigned sbin[256];
    __shared__ int s_chunk;
    __shared__ unsigned s_before;
    int tid = threadIdx.x;
    // chunk t = bins [t*256, (t+1)*256)
    unsigned sum = 0;
    const uint4* hp = (const uint4*)&g_hist14[tid * 256];
#pragma unroll 8
    for (int i = 0; i < 64; i++) { uint4 v = hp[i]; sum += v.x + v.y + v.z + v.w; }
    s[1023 - tid] = sum;            // descending chunk order
    __syncthreads();
    for (int off = 1; off < 1024; off <<= 1) {
        unsigned v = s[tid] + ((tid >= off) ? s[tid - off] : 0);
        __syncthreads();
        s[tid] = v;
        __syncthreads();
    }
    // s[t] = count of keys in chunks >= (1023-t); find crossing chunk
    if (s[tid] >= TOPK && (tid == 0 || s[tid - 1] < TOPK)) {
        s_chunk = 1023 - tid;
        s_before = (tid > 0) ? s[tid - 1] : 0;
    }
    __syncthreads();
    int chunk = s_chunk;
    if (tid < 256) sbin[tid] = g_hist14[chunk*256 + tid];
    __syncthreads();
    if (tid == 0) {
        unsigned cum = s_before;
        for (int b = 255; b >= 0; b--) {
            cum += sbin[b];
            if (cum >= TOPK) { g_state[0] = ((unsigned)(chunk*256 + b)) << SBITS; break; }
        }
    }
}

// ---------------- 5: compact + (last block) bitonic sort + valid-partition ----------------
__global__ __launch_bounds__(1024) void csp_kernel() {
    __shared__ unsigned long long s[4096];
    __shared__ int sv[2048];
    __shared__ unsigned s_last;
    int tid = threadIdx.x;
    unsigned T = g_state[0];
    for (int i = blockIdx.x*blockDim.x + tid; i < NANCH; i += gridDim.x*blockDim.x) {
        unsigned k = g_key[i];
        if (k >= T) {
            unsigned pos = atomicAdd(&g_cnt[0], 1u);
            if (pos < 4096)
                g_pairs[pos] = ((unsigned long long)k << 32) | (unsigned)(~(unsigned)i);
        }
    }
    __threadfence();
    if (tid == 0) s_last = atomicAdd(&g_done[4], 1u);
    __syncthreads();
    if (s_last != gridDim.x - 1) return;

    unsigned n = min(*((volatile unsigned*)&g_cnt[0]), 4096u);
#pragma unroll
    for (int r = 0; r < 4; r++) {
        int i = tid + r*1024;
        s[i] = ((unsigned)i < n) ? *((volatile unsigned long long*)&g_pairs[i]) : 0ull;
    }
    __syncthreads();
    for (unsigned k2 = 2; k2 <= 4096; k2 <<= 1) {
        for (unsigned j = k2 >> 1; j > 0; j >>= 1) {
            for (int i = tid; i < 4096; i += 1024) {
                int ixj = i ^ (int)j;
                if (ixj > i) {
                    unsigned long long a = s[i], b = s[ixj];
                    bool up = ((i & k2) == 0);
                    if ((a < b) == up) { s[i] = b; s[ixj] = a; }
                }
            }
            __syncthreads();
        }
    }

    float bx[2][4], sc[2];
    int vld[2];
    int rr[2] = { tid, tid + 1024 };
#pragma unroll
    for (int e = 0; e < 2; e++) {
        int r = rr[e];
        vld[e] = 0; sc[e] = 0.f;
        bx[e][0] = bx[e][1] = bx[e][2] = bx[e][3] = 0.f;
        if (r < TOPK) {
            unsigned long long t = s[r];
            unsigned idx = ~(unsigned)(t & 0xffffffffull);
            sc[e] = __uint_as_float((unsigned)(t >> 32));
            bx[e][0] = g_boxes[(size_t)idx*4+0];
            bx[e][1] = g_boxes[(size_t)idx*4+1];
            bx[e][2] = g_boxes[(size_t)idx*4+2];
            bx[e][3] = g_boxes[(size_t)idx*4+3];
            vld[e] = ((bx[e][2]-bx[e][0]) >= 16.f && (bx[e][3]-bx[e][1]) >= 16.f) ? 1 : 0;
        }
        sv[r] = vld[e];
    }
    __syncthreads();
    for (int off = 1; off < 2048; off <<= 1) {
        int a0 = sv[rr[0]] + ((rr[0] >= off) ? sv[rr[0]-off] : 0);
        int a1 = sv[rr[1]] + ((rr[1] >= off) ? sv[rr[1]-off] : 0);
        __syncthreads();
        sv[rr[0]] = a0; sv[rr[1]] = a1;
        __syncthreads();
    }
    int V = sv[TOPK-1];
    if (tid == 0) g_cnt[2] = (unsigned)V;
#pragma unroll
    for (int e = 0; e < 2; e++) {
        int r = rr[e];
        if (r < TOPK) {
            int pos = vld[e] ? (sv[r]-1) : (V + (r - sv[r]));
            g_sb[pos*4+0] = bx[e][0]; g_sb[pos*4+1] = bx[e][1];
            g_sb[pos*4+2] = bx[e][2]; g_sb[pos*4+3] = bx[e][3];
            g_ss[pos] = sc[e];
        }
    }
}

// ---------------- 7: NMS suppression mask matrix ----------------
__global__ void mask_kernel() {
    __shared__ float cb[64][4];
    int t = threadIdx.x;
    int rbase = blockIdx.y*64, cbase = blockIdx.x*64;
    if (cbase + t < TOPK) {
        cb[t][0] = g_sb[(cbase+t)*4+0];
        cb[t][1] = g_sb[(cbase+t)*4+1];
        cb[t][2] = g_sb[(cbase+t)*4+2];
        cb[t][3] = g_sb[(cbase+t)*4+3];
    } else {
        cb[t][0] = cb[t][1] = cb[t][2] = cb[t][3] = 0.f;
    }
    __syncthreads();
    int r = rbase + t;
    if (r >= TOPK) return;
    float r0 = g_sb[r*4+0], r1 = g_sb[r*4+1], r2 = g_sb[r*4+2], r3 = g_sb[r*4+3];
    float areaR = (r2-r0)*(r3-r1);
    unsigned long long bits = 0;
#pragma unroll 4
    for (int j = 0; j < 64; j++) {
        int c = cbase + j;
        if (c > r && c < TOPK) {
            float lt0 = fmaxf(r0, cb[j][0]), lt1 = fmaxf(r1, cb[j][1]);
            float rb0 = fminf(r2, cb[j][2]), rb1 = fminf(r3, cb[j][3]);
            float w = fmaxf(rb0-lt0, 0.f), h = fmaxf(rb1-lt1, 0.f);
            float inter = w*h;
            float areaC = (cb[j][2]-cb[j][0])*(cb[j][3]-cb[j][1]);
            float iou = inter / (areaR + areaC - inter + 1e-9f);
            if (iou > NMS_TH) bits |= (1ull << j);
        }
    }
    g_mask[(size_t)r*32 + blockIdx.x] = bits;
}

// ---------------- 8: greedy NMS scan (deep ring prefetch) + final scatter ----------------
#define NMSD 16
__global__ __launch_bounds__(1024) void final_kernel(float* __restrict__ out) {
    __shared__ unsigned long long keepw[32];
    __shared__ int sv[2048];
    int tid = threadIdx.x;
    for (int i = tid; i < OUTK*5; i += 1024) out[i] = 0.f;
    unsigned V = g_cnt[2];
    if (tid < 32) {
        int lane = tid;
        unsigned long long remove = 0;
        unsigned long long ring[NMSD];
#pragma unroll
        for (int d = 0; d < NMSD; d++) ring[d] = g_mask[(size_t)d*32 + lane];
        for (int i0 = 0; i0 < TOPK; i0 += NMSD) {
#pragma unroll
            for (int d = 0; d < NMSD; d++) {
                int i = i0 + d;
                unsigned long long cur = ring[d];
                if (i + NMSD < TOPK)
                    ring[d] = g_mask[(size_t)(i + NMSD)*32 + lane];
                unsigned long long rw = __shfl_sync(0xffffffffu, remove, i >> 6);
                bool k = ((unsigned)i < V) && !((rw >> (i & 63)) & 1ull);
                if (k) remove |= cur;
            }
        }
        keepw[lane] = remove;
    }
    __syncthreads();
    int rr[2] = { tid, tid + 1024 };
    int kp[2];
#pragma unroll
    for (int e = 0; e < 2; e++) {
        int r = rr[e];
        kp[e] = ((unsigned)r < V) && !((keepw[r >> 6] >> (r & 63)) & 1ull);
        sv[r] = kp[e];
    }
    __syncthreads();
    for (int off = 1; off < 2048; off <<= 1) {
        int a0 = sv[rr[0]] + ((rr[0] >= off) ? sv[rr[0]-off] : 0);
        int a1 = sv[rr[1]] + ((rr[1] >= off) ? sv[rr[1]-off] : 0);
        __syncthreads();
        sv[rr[0]] = a0; sv[rr[1]] = a1;
        __syncthreads();
    }
#pragma unroll
    for (int e = 0; e < 2; e++) {
        int r = rr[e];
        if (r < TOPK && kp[e]) {
            int pos = sv[r] - 1;
            if (pos < OUTK) {
                out[pos*4+0] = g_sb[r*4+0];
                out[pos*4+1] = g_sb[r*4+1];
                out[pos*4+2] = g_sb[r*4+2];
                out[pos*4+3] = g_sb[r*4+3];
                out[OUTK*4 + pos] = g_ss[r];
            }
        }
    }
}

// ---------------- launch ----------------
extern "C" void kernel_launch(void* const* d_in, const int* in_sizes, int n_in,
                              void* d_out, int out_size) {
    // inputs: 0 image, 1 feat, 2 conv_w, 3 conv_b, 4 cls_w, 5 cls_b, 6 reg_w, 7 reg_b
    const float* feat   = (const float*)d_in[1];
    const float* conv_w = (const float*)d_in[2];
    const float* conv_b = (const float*)d_in[3];
    const float* cls_w  = (const float*)d_in[4];
    const float* cls_b  = (const float*)d_in[5];
    const float* reg_w  = (const float*)d_in[6];
    const float* reg_b  = (const float*)d_in[7];
    float* out = (float*)d_out;

    int prep_n = GATOT + 2304*256;
    prep_kernel<<<(prep_n + 511)/512, 512>>>(feat, conv_w);     // (1)
    init_kernel<<<64, 1024>>>();                                // (2)
    conv3_kernel<<<dim3((NPAD + BN - 1)/BN, CCH/BM), 256>>>(conv_b);   // (3)
    heads_kernel<<<(NPIX + HB - 1)/HB, HB>>>(cls_w, cls_b, reg_w, reg_b); // (4) <- ncu capture
    hist14_kernel<<<360, 256>>>();                              // (5)
    pick14_kernel<<<1, 1024>>>();                               // (6)
    csp_kernel<<<90, 1024>>>();                                 // (7)
    mask_kernel<<<dim3(32, 32), 64>>>();                        // (8)
    final_kernel<<<1, 1024>>>(out);                             // (9)
}

// round 17
// speedup vs baseline: 1.0794x; 1.0794x over previous
#include <cuda_runtime.h>
#include <cuda_bf16.h>
#include <math.h>
#include <stdint.h>

// ---------------- problem constants ----------------
#define FEAT   200
#define PADW   202
#define NPIX   (FEAT*FEAT)          // 40000
#define NPAD   (PADW*PADW)          // 40804
#define CCH    256
#define NA     9
#define NANCH  (NPIX*NA)            // 360000
#define TOPK   2000
#define OUTK   1000
#define NMS_TH 0.7f
#define BBOX_CLIP 4.135166556742356f
#define IMGSZ  1600.0f

// ---------------- packed f32x2 helpers (Blackwell FFMA2) ----------------
#define FMA2(acc, a, b) asm("fma.rn.f32x2 %0, %1, %2, %0;" : "+l"(acc) : "l"(a), "l"(b))

__device__ __forceinline__ unsigned long long splat2(float v) {
    unsigned long long r; asm("mov.b64 %0, {%1, %1};" : "=l"(r) : "f"(v)); return r;
}
__device__ __forceinline__ float2 unpack2(unsigned long long p) {
    float2 f; asm("mov.b64 {%0, %1}, %2;" : "=f"(f.x), "=f"(f.y) : "l"(p)); return f;
}

#define CP_ASYNC16(dst_u32, src_ptr) \
    asm volatile("cp.async.cg.shared.global [%0], [%1], 16;\n" :: "r"(dst_u32), "l"(src_ptr))
#define CP_COMMIT() asm volatile("cp.async.commit_group;\n")
#define CP_WAIT1()  asm volatile("cp.async.wait_group 1;\n")
#define CP_WAIT0()  asm volatile("cp.async.wait_group 0;\n")

// ---------------- scratch (device globals; no allocation allowed) ----------------
#define GAPAD 256
#define GTAIL 512
#define GATOT (GAPAD + CCH*NPAD + GTAIL)
__device__ __align__(16) float g_padA[GATOT];     // guarded padded feature map
__device__ __align__(16) float g_wT[2304*256];    // transposed conv weights [k][m]
__device__ float g_x[CCH*NPIX];          // relu(conv3x3) output, [c][p]
__device__ float g_boxes[NANCH*4];       // clipped proposals
__device__ unsigned g_key[NANCH];        // sortable sigmoid-score bits
__device__ unsigned g_hist[4][256];
__device__ unsigned g_state[4];          // [0]=threshold
__device__ unsigned g_cnt[4];            // [0]=pair count, [2]=valid count V
__device__ unsigned g_done[8];           // barrier counters
__device__ unsigned long long g_pairs[4096];
__device__ float g_sb[TOPK*4];           // boxes, valid-partitioned, rank order
__device__ float g_ss[TOPK];             // scores, same order
__device__ unsigned long long g_mask[TOPK*32];

// ---------------- 0: guard-padded feature map + weight transpose ----------------
__global__ void prep_kernel(const float* __restrict__ feat, const float* __restrict__ w) {
    int i = blockIdx.x*blockDim.x + threadIdx.x;
    if (i < GATOT) {
        float v = 0.f;
        int j = i - GAPAD;
        if (j >= 0 && j < CCH*NPAD) {
            int c = j / NPAD, q = j % NPAD;
            int y = q / PADW, x = q % PADW;
            if (y >= 1 && y <= FEAT && x >= 1 && x <= FEAT)
                v = feat[c*NPIX + (y-1)*FEAT + (x-1)];
        }
        g_padA[i] = v;
    } else {
        int j = i - GATOT;
        if (j < 2304*256) {
            int m = j / 2304, k = j % 2304;
            g_wT[k*256 + m] = w[j];
        }
    }
}

// ---------------- selection-state init ----------------
__global__ void init_kernel() {
    int tid = threadIdx.x;
    if (tid < 1024) ((unsigned*)g_hist)[tid] = 0;
    if (tid < 4) g_cnt[tid] = 0;
    if (tid < 8) g_done[tid] = 0;
    if (tid == 0) { g_state[0] = 0; g_state[1] = TOPK; }
}

// ---------------- 1: conv3x3 + bias + relu, cp.async double-buffered implicit GEMM ----------------
// CK=8: 32 chunks. (measured ~811us)
#define BM 128
#define BN 144
#define TPX 9
#define BWIN 560   // per-channel pixel window [q0-208, q0+352)
#define CK 8
#define NCHUNK (CCH/CK)   // 32
__global__ __launch_bounds__(256, 2) void conv3_kernel(const float* __restrict__ bias) {
    __shared__ __align__(16) float sW[2][CK*9][BM];   // [buf][k in chunk][m]  (72 rows)
    __shared__ __align__(16) float sB[2][CK][BWIN];   // [buf][c][pixel window]
    const int tid = threadIdx.x;
    const int tx = tid & 15, ty = tid >> 4;
    const int m0 = blockIdx.y * BM;
    const int q0 = blockIdx.x * BN;
    const int p0 = tx * TPX;                          // 9 consecutive pixels per thread

    unsigned long long acc[4][TPX];
#pragma unroll
    for (int a = 0; a < 4; a++)
#pragma unroll
        for (int b = 0; b < TPX; b++) acc[a][b] = 0ull;

#define STAGE(BUF, CKI) do {                                                        \
        for (int idx = tid; idx < 2304; idx += 256) {                               \
            int row = idx >> 5, c8 = idx & 31;                                      \
            uint32_t d = (uint32_t)__cvta_generic_to_shared(&sW[BUF][row][c8*4]);   \
            const float* s = g_wT + ((CKI)*72 + row)*256 + m0 + c8*4;               \
            CP_ASYNC16(d, s);                                                       \
        }                                                                           \
        for (int idx = tid; idx < 1120; idx += 256) {                               \
            int c = idx / 140, o4 = idx % 140;                                      \
            uint32_t d = (uint32_t)__cvta_generic_to_shared(&sB[BUF][c][o4*4]);     \
            const float* s = g_padA + GAPAD + (size_t)((CKI)*CK + c)*NPAD           \
                             + (q0 - 208) + o4*4;                                   \
            CP_ASYNC16(d, s);                                                       \
        }                                                                           \
        CP_COMMIT();                                                                \
    } while (0)

    STAGE(0, 0);
    int buf = 0;
    for (int ck = 0; ck < NCHUNK; ck++) {
        if (ck + 1 < NCHUNK) { STAGE(buf ^ 1, ck + 1); CP_WAIT1(); }
        else                 { CP_WAIT0(); }
        __syncthreads();
#pragma unroll
        for (int c = 0; c < CK; c++) {
#pragma unroll
            for (int ky = 0; ky < 3; ky++) {
                const float* bb = &sB[buf][c][p0 + 202*ky + 5];
                unsigned long long spx[TPX + 2];
#pragma unroll
                for (int u = 0; u < TPX + 2; u++) spx[u] = splat2(bb[u]);
#pragma unroll
                for (int kx = 0; kx < 3; kx++) {
                    const int kk = c*9 + ky*3 + kx;
                    ulonglong2 WA = *(const ulonglong2*)&sW[buf][kk][ty*4];
                    ulonglong2 WB = *(const ulonglong2*)&sW[buf][kk][64 + ty*4];
#pragma unroll
                    for (int j = 0; j < TPX; j++) {
                        unsigned long long bs = spx[kx + j];
                        FMA2(acc[0][j], WA.x, bs);
                        FMA2(acc[1][j], WA.y, bs);
                        FMA2(acc[2][j], WB.x, bs);
                        FMA2(acc[3][j], WB.y, bs);
                    }
                }
            }
        }
        __syncthreads();
        buf ^= 1;
    }
#undef STAGE
#pragma unroll
    for (int cp = 0; cp < 4; cp++) {
        int mb = m0 + (cp >> 1)*64 + ty*4 + (cp & 1)*2;
        float bv0 = bias[mb], bv1 = bias[mb + 1];
#pragma unroll
        for (int j = 0; j < TPX; j++) {
            int q = q0 + p0 + j;
            if (q < NPAD) {
                int y = q / PADW, x = q % PADW;
                if (y >= 1 && y <= FEAT && x >= 1 && x <= FEAT) {
                    float2 v = unpack2(acc[cp][j]);
                    int p = (y-1)*FEAT + (x-1);
                    g_x[(size_t)mb*NPIX + p]     = fmaxf(v.x + bv0, 0.f);
                    g_x[(size_t)(mb+1)*NPIX + p] = fmaxf(v.y + bv1, 0.f);
                }
            }
        }
    }
}

// ---------------- 2: heads (45x256 GEMM, FFMA2) + anchors + deltas + clip + sigmoid ----------------
__device__ __forceinline__ void process_pixel(int p, float* L,
                                              const float* sbias) {
    if (p >= NPIX) return;
#pragma unroll
    for (int m = 0; m < 45; m++) L[m] += sbias[m];
    int y = p / FEAT, x = p % FEAT;
    float sx = x * 8.f, sy = y * 8.f;
#pragma unroll
    for (int a = 0; a < NA; a++) {
        int ai = a / 3, si = a % 3;
        float ar = (ai == 0) ? 0.5f : (ai == 1 ? 1.f : 2.f);
        float sc = (si == 0) ? 128.f : (si == 1 ? 256.f : 512.f);
        float hr = sqrtf(ar), wr = 1.f/hr;
        float ws = wr*sc, hs = hr*sc;
        float bx1 = rintf(-ws*0.5f), by1 = rintf(-hs*0.5f);
        float bx2 = rintf( ws*0.5f), by2 = rintf( hs*0.5f);
        float ax1 = sx + bx1, ay1 = sy + by1, ax2 = sx + bx2, ay2 = sy + by2;
        float w = ax2 - ax1, h = ay2 - ay1;
        float cx = ax1 + 0.5f*w, cy = ay1 + 0.5f*h;
        float dx = L[9 + a*4 + 0], dy = L[9 + a*4 + 1];
        float dw = fminf(L[9 + a*4 + 2], BBOX_CLIP);
        float dh = fminf(L[9 + a*4 + 3], BBOX_CLIP);
        float pcx = dx*w + cx, pcy = dy*h + cy;
        float pw = expf(dw)*w, ph = expf(dh)*h;
        float x1 = pcx - 0.5f*pw, y1 = pcy - 0.5f*ph;
        float x2 = pcx + 0.5f*pw, y2 = pcy + 0.5f*ph;
        x1 = fminf(fmaxf(x1, 0.f), IMGSZ);
        y1 = fminf(fmaxf(y1, 0.f), IMGSZ);
        x2 = fminf(fmaxf(x2, 0.f), IMGSZ);
        y2 = fminf(fmaxf(y2, 0.f), IMGSZ);
        int o = p*NA + a;
        g_boxes[o*4+0] = x1; g_boxes[o*4+1] = y1;
        g_boxes[o*4+2] = x2; g_boxes[o*4+3] = y2;
        float l = L[a];
        float s = 1.f / (1.f + expf(-l));
        g_key[o] = __float_as_uint(s);     // s in (0,1): bit pattern is order-preserving
    }
}

// 1 pixel/thread, block=128 (grid 313 -> 2 CTAs/SM), c-loop unrolled x8 (MLP=8). measured ~71us
#define HB 128
__global__ __launch_bounds__(HB) void heads_kernel(const float* __restrict__ clsw,
                                                   const float* __restrict__ clsb,
                                                   const float* __restrict__ regw,
                                                   const float* __restrict__ regb) {
    __shared__ __align__(16) unsigned long long sw2[CCH][24];
    __shared__ float sbias[48];
    const int tid = threadIdx.x;
    for (int i = tid; i < CCH*24; i += HB) {
        int c = i / 24, mp = i % 24;
        float v0 = 0.f, v1 = 0.f;
        int m0i = 2*mp, m1i = 2*mp + 1;
        if (m0i < 9)       v0 = clsw[m0i*CCH + c];
        else if (m0i < 45) v0 = regw[(m0i-9)*CCH + c];
        if (m1i < 9)       v1 = clsw[m1i*CCH + c];
        else if (m1i < 45) v1 = regw[(m1i-9)*CCH + c];
        unsigned long long pr;
        asm("mov.b64 %0, {%1, %2};" : "=l"(pr) : "f"(v0), "f"(v1));
        sw2[c][mp] = pr;
    }
    if (tid < 48) sbias[tid] = (tid < 9) ? clsb[tid] : ((tid < 45) ? regb[tid - 9] : 0.f);
    __syncthreads();

    int p = blockIdx.x*HB + tid;
    bool live = (p < NPIX);
    int pc = live ? p : 0;                  // clamp: dead threads compute garbage, never store
    unsigned long long A2[24];
#pragma unroll
    for (int m = 0; m < 24; m++) A2[m] = 0ull;
    for (int c = 0; c < CCH; c += 8) {
        // batch 8 independent loads up front (MLP=8)
        float xv[8];
#pragma unroll
        for (int u = 0; u < 8; u++) xv[u] = g_x[(size_t)(c+u)*NPIX + pc];
        unsigned long long xs[8];
#pragma unroll
        for (int u = 0; u < 8; u++) xs[u] = splat2(xv[u]);
#pragma unroll
        for (int u = 0; u < 8; u++) {
            const ulonglong2* wr = (const ulonglong2*)&sw2[c + u][0];
#pragma unroll
            for (int q = 0; q < 12; q++) {
                ulonglong2 wv = wr[q];
                FMA2(A2[2*q],   wv.x, xs[u]);
                FMA2(A2[2*q+1], wv.y, xs[u]);
            }
        }
    }
    float LA[48];
#pragma unroll
    for (int m = 0; m < 24; m++) {
        float2 v = unpack2(A2[m]);
        LA[2*m] = v.x; LA[2*m+1] = v.y;
    }
    process_pixel(live ? p : NPIX, LA, sbias);
}

// ---------------- 4: fused 4-pass MSB radix select (single persistent kernel) ----------------
// All 296 blocks co-resident; spin barrier between digit passes; every block
// recomputes the identical pick locally (no extra global sync needed).
#define RGRID 296
__global__ __launch_bounds__(256) void radix_select_kernel() {
    __shared__ unsigned h[256];
    __shared__ unsigned s[256];
    __shared__ unsigned s_ch, s_cum;
    const int tid = threadIdx.x;
    unsigned prefix = 0, need = TOPK;
#pragma unroll
    for (int d = 0; d < 4; d++) {
        h[tid] = 0;
        __syncthreads();
        const int sh = 24 - 8*d;
        for (int i = blockIdx.x*blockDim.x + tid; i < NANCH; i += RGRID*256) {
            unsigned k = g_key[i];
            bool ok = (d == 0) || ((k >> (sh + 8)) == prefix);
            if (ok) atomicAdd(&h[(k >> sh) & 255], 1u);
        }
        __syncthreads();
        if (h[tid]) atomicAdd(&g_hist[d][tid], h[tid]);
        __threadfence();
        if (tid == 0) {
            atomicAdd(&g_done[d], 1u);
            while (*((volatile unsigned*)&g_done[d]) < RGRID) { }
        }
        __syncthreads();
        // local pick: suffix scan over descending bins of the COMPLETE histogram
        s[tid] = *((volatile unsigned*)&g_hist[d][255 - tid]);
        __syncthreads();
        for (int off = 1; off < 256; off <<= 1) {
            unsigned v = s[tid] + ((tid >= off) ? s[tid - off] : 0);
            __syncthreads();
            s[tid] = v;
            __syncthreads();
        }
        if (s[tid] >= need && (tid == 0 || s[tid - 1] < need)) {
            s_ch = (unsigned)(255 - tid);
            s_cum = (tid > 0) ? s[tid - 1] : 0;
        }
        __syncthreads();
        prefix = (prefix << 8) | s_ch;
        need -= s_cum;
        __syncthreads();
    }
    if (blockIdx.x == 0 && tid == 0) g_state[0] = prefix;   // final threshold
}

// ---------------- 5: compact + (last block) bitonic sort + valid-partition ----------------
__global__ __launch_bounds__(1024) void csp_kernel() {
    __shared__ unsigned long long s[4096];
    __shared__ int sv[2048];
    __shared__ unsigned s_last;
    int tid = threadIdx.x;
    unsigned T = g_state[0];
    for (int i = blockIdx.x*blockDim.x + tid; i < NANCH; i += gridDim.x*blockDim.x) {
        unsigned k = g_key[i];
        if (k >= T) {
            unsigned pos = atomicAdd(&g_cnt[0], 1u);
            if (pos < 4096)
                g_pairs[pos] = ((unsigned long long)k << 32) | (unsigned)(~(unsigned)i);
        }
    }
    __threadfence();
    if (tid == 0) s_last = atomicAdd(&g_done[4], 1u);
    __syncthreads();
    if (s_last != gridDim.x - 1) return;

    unsigned n = min(*((volatile unsigned*)&g_cnt[0]), 4096u);
#pragma unroll
    for (int r = 0; r < 4; r++) {
        int i = tid + r*1024;
        s[i] = ((unsigned)i < n) ? *((volatile unsigned long long*)&g_pairs[i]) : 0ull;
    }
    __syncthreads();
    for (unsigned k2 = 2; k2 <= 4096; k2 <<= 1) {
        for (unsigned j = k2 >> 1; j > 0; j >>= 1) {
            for (int i = tid; i < 4096; i += 1024) {
                int ixj = i ^ (int)j;
                if (ixj > i) {
                    unsigned long long a = s[i], b = s[ixj];
                    bool up = ((i & k2) == 0);
                    if ((a < b) == up) { s[i] = b; s[ixj] = a; }
                }
            }
            __syncthreads();
        }
    }

    float bx[2][4], sc[2];
    int vld[2];
    int rr[2] = { tid, tid + 1024 };
#pragma unroll
    for (int e = 0; e < 2; e++) {
        int r = rr[e];
        vld[e] = 0; sc[e] = 0.f;
        bx[e][0] = bx[e][1] = bx[e][2] = bx[e][3] = 0.f;
        if (r < TOPK) {
            unsigned long long t = s[r];
            unsigned idx = ~(unsigned)(t & 0xffffffffull);
            sc[e] = __uint_as_float((unsigned)(t >> 32));
            bx[e][0] = g_boxes[(size_t)idx*4+0];
            bx[e][1] = g_boxes[(size_t)idx*4+1];
            bx[e][2] = g_boxes[(size_t)idx*4+2];
            bx[e][3] = g_boxes[(size_t)idx*4+3];
            vld[e] = ((bx[e][2]-bx[e][0]) >= 16.f && (bx[e][3]-bx[e][1]) >= 16.f) ? 1 : 0;
        }
        sv[r] = vld[e];
    }
    __syncthreads();
    for (int off = 1; off < 2048; off <<= 1) {
        int a0 = sv[rr[0]] + ((rr[0] >= off) ? sv[rr[0]-off] : 0);
        int a1 = sv[rr[1]] + ((rr[1] >= off) ? sv[rr[1]-off] : 0);
        __syncthreads();
        sv[rr[0]] = a0; sv[rr[1]] = a1;
        __syncthreads();
    }
    int V = sv[TOPK-1];
    if (tid == 0) g_cnt[2] = (unsigned)V;
#pragma unroll
    for (int e = 0; e < 2; e++) {
        int r = rr[e];
        if (r < TOPK) {
            int pos = vld[e] ? (sv[r]-1) : (V + (r - sv[r]));
            g_sb[pos*4+0] = bx[e][0]; g_sb[pos*4+1] = bx[e][1];
            g_sb[pos*4+2] = bx[e][2]; g_sb[pos*4+3] = bx[e][3];
            g_ss[pos] = sc[e];
        }
    }
}

// ---------------- 7: NMS suppression mask matrix ----------------
__global__ void mask_kernel() {
    __shared__ float cb[64][4];
    int t = threadIdx.x;
    int rbase = blockIdx.y*64, cbase = blockIdx.x*64;
    if (cbase + t < TOPK) {
        cb[t][0] = g_sb[(cbase+t)*4+0];
        cb[t][1] = g_sb[(cbase+t)*4+1];
        cb[t][2] = g_sb[(cbase+t)*4+2];
        cb[t][3] = g_sb[(cbase+t)*4+3];
    } else {
        cb[t][0] = cb[t][1] = cb[t][2] = cb[t][3] = 0.f;
    }
    __syncthreads();
    int r = rbase + t;
    if (r >= TOPK) return;
    float r0 = g_sb[r*4+0], r1 = g_sb[r*4+1], r2 = g_sb[r*4+2], r3 = g_sb[r*4+3];
    float areaR = (r2-r0)*(r3-r1);
    unsigned long long bits = 0;
#pragma unroll 4
    for (int j = 0; j < 64; j++) {
        int c = cbase + j;
        if (c > r && c < TOPK) {
            float lt0 = fmaxf(r0, cb[j][0]), lt1 = fmaxf(r1, cb[j][1]);
            float rb0 = fminf(r2, cb[j][2]), rb1 = fminf(r3, cb[j][3]);
            float w = fmaxf(rb0-lt0, 0.f), h = fmaxf(rb1-lt1, 0.f);
            float inter = w*h;
            float areaC = (cb[j][2]-cb[j][0])*(cb[j][3]-cb[j][1]);
            float iou = inter / (areaR + areaC - inter + 1e-9f);
            if (iou > NMS_TH) bits |= (1ull << j);
        }
    }
    g_mask[(size_t)r*32 + blockIdx.x] = bits;
}

// ---------------- 8: greedy NMS scan (deep ring prefetch) + final scatter ----------------
#define NMSD 16
__global__ __launch_bounds__(1024) void final_kernel(float* __restrict__ out) {
    __shared__ unsigned long long keepw[32];
    __shared__ int sv[2048];
    int tid = threadIdx.x;
    for (int i = tid; i < OUTK*5; i += 1024) out[i] = 0.f;
    unsigned V = g_cnt[2];
    if (tid < 32) {
        int lane = tid;
        unsigned long long remove = 0;
        unsigned long long ring[NMSD];
#pragma unroll
        for (int d = 0; d < NMSD; d++) ring[d] = g_mask[(size_t)d*32 + lane];
        for (int i0 = 0; i0 < TOPK; i0 += NMSD) {
#pragma unroll
            for (int d = 0; d < NMSD; d++) {
                int i = i0 + d;
                unsigned long long cur = ring[d];
                if (i + NMSD < TOPK)
                    ring[d] = g_mask[(size_t)(i + NMSD)*32 + lane];
                unsigned long long rw = __shfl_sync(0xffffffffu, remove, i >> 6);
                bool k = ((unsigned)i < V) && !((rw >> (i & 63)) & 1ull);
                if (k) remove |= cur;
            }
        }
        keepw[lane] = remove;
    }
    __syncthreads();
    int rr[2] = { tid, tid + 1024 };
    int kp[2];
#pragma unroll
    for (int e = 0; e < 2; e++) {
        int r = rr[e];
        kp[e] = ((unsigned)r < V) && !((keepw[r >> 6] >> (r & 63)) & 1ull);
        sv[r] = kp[e];
    }
    __syncthreads();
    for (int off = 1; off < 2048; off <<= 1) {
        int a0 = sv[rr[0]] + ((rr[0] >= off) ? sv[rr[0]-off] : 0);
        int a1 = sv[rr[1]] + ((rr[1] >= off) ? sv[rr[1]-off] : 0);
        __syncthreads();
        sv[rr[0]] = a0; sv[rr[1]] = a1;
        __syncthreads();
    }
#pragma unroll
    for (int e = 0; e < 2; e++) {
        int r = rr[e];
        if (r < TOPK && kp[e]) {
            int pos = sv[r] - 1;
            if (pos < OUTK) {
                out[pos*4+0] = g_sb[r*4+0];
                out[pos*4+1] = g_sb[r*4+1];
                out[pos*4+2] = g_sb[r*4+2];
                out[pos*4+3] = g_sb[r*4+3];
                out[OUTK*4 + pos] = g_ss[r];
            }
        }
    }
}

// ---------------- launch ----------------
extern "C" void kernel_launch(void* const* d_in, const int* in_sizes, int n_in,
                              void* d_out, int out_size) {
    // inputs: 0 image, 1 feat, 2 conv_w, 3 conv_b, 4 cls_w, 5 cls_b, 6 reg_w, 7 reg_b
    const float* feat   = (const float*)d_in[1];
    const float* conv_w = (const float*)d_in[2];
    const float* conv_b = (const float*)d_in[3];
    const float* cls_w  = (const float*)d_in[4];
    const float* cls_b  = (const float*)d_in[5];
    const float* reg_w  = (const float*)d_in[6];
    const float* reg_b  = (const float*)d_in[7];
    float* out = (float*)d_out;

    int prep_n = GATOT + 2304*256;
    prep_kernel<<<(prep_n + 511)/512, 512>>>(feat, conv_w);     // (1)
    init_kernel<<<1, 1024>>>();                                 // (2)
    conv3_kernel<<<dim3((NPAD + BN - 1)/BN, CCH/BM), 256>>>(conv_b);   // (3)
    heads_kernel<<<(NPIX + HB - 1)/HB, HB>>>(cls_w, cls_b, reg_w, reg_b); // (4) <- ncu capture
    radix_select_kernel<<<RGRID, 256>>>();                      // (5)
    csp_kernel<<<90, 1024>>>();                                 // (6)
    mask_kernel<<<dim3(32, 32), 64>>>();                        // (7)
    final_kernel<<<1, 1024>>>(out);                             // (8)
}